// round 15
// baseline (speedup 1.0000x reference)
#include <cuda_runtime.h>
#include <cuda_fp16.h>
#include <cuda_bf16.h>
#include <math.h>
#include <stdint.h>

#define QROWS 4096
#define DIM   512
#define TWO_D 1024
#define NKEYS 32768
#define TOPK  64
#define EPSF  1e-8f
#define NBINS 2048
#define CAP   512

// ---- coherence GEMM: 128x128 tile, 3-stage cp.async ----
#define GTM 128
#define GTN 128
#define TILE_BYTES (128 * 144)
#define STAGE_BYTES (2 * TILE_BYTES)        // 36864
#define NSTG 3
#define GEMM_SMEM (NSTG * STAGE_BYTES)      // 110592
#define KCHUNKS 16

// ---- out-projection split-bf16 GEMM: K = 3072 ----
#define PKO 3072
#define PGEMM_SMEM (2 * STAGE_BYTES)        // 73728, 2-stage

// ---- topk dynamic smem layout (bytes) ----
#define TK_ROW    0                          // 32768 half = 65536
#define TK_HIST   65536                      // 2048 int   = 8192
#define TK_QS     (65536 + 8192)             // 1024 float = 4096
#define TK_CANDD  (TK_QS + 4096)             // CAP double = 4096
#define TK_CANDI  (TK_CANDD 	+ CAP * 8)      // CAP int    = 2048
#define TK_SMEM   (TK_CANDI + CAP * 4)       // ~83968

// ---------------- scratch (no allocations allowed) ----------------
__device__ float  g_q[(size_t)QROWS * TWO_D];
__device__ __nv_bfloat16 g_qh[(size_t)QROWS * TWO_D];
__device__ __nv_bfloat16 g_kh[(size_t)NKEYS * TWO_D];
__device__ double g_qmagd[QROWS];
__device__ float  g_qmagf[QROWS];
__device__ double g_kmagd[NKEYS];
__device__ float  g_kmagf[NKEYS];
__device__ __half g_scoresh[(size_t)QROWS * NKEYS];
__device__ float  g_norm[(size_t)QROWS * TWO_D];
__device__ __nv_bfloat16 g_A2o[(size_t)QROWS * PKO];
__device__ __nv_bfloat16 g_B2o[(size_t)TWO_D * PKO];

// ---------------- helpers ----------------
__device__ __forceinline__ uint32_t smem_u32(const void* p) {
    uint32_t a;
    asm("{ .reg .u64 t; cvta.to.shared.u64 t, %1; cvt.u32.u64 %0, t; }" : "=r"(a) : "l"(p));
    return a;
}
__device__ __forceinline__ void cpasync16(uint32_t dst, const void* src) {
    asm volatile("cp.async.cg.shared.global [%0], [%1], 16;" :: "r"(dst), "l"(src) : "memory");
}
__device__ __forceinline__ void ldmx4(uint32_t* r, uint32_t a) {
    asm volatile("ldmatrix.sync.aligned.m8n8.x4.shared.b16 {%0,%1,%2,%3}, [%4];"
                 : "=r"(r[0]), "=r"(r[1]), "=r"(r[2]), "=r"(r[3]) : "r"(a));
}
__device__ __forceinline__ void mma_bf16_b2(float* d, const uint32_t* a, uint32_t b0, uint32_t b1) {
    asm volatile(
        "mma.sync.aligned.m16n8k16.row.col.f32.bf16.bf16.f32 "
        "{%0,%1,%2,%3}, {%4,%5,%6,%7}, {%8,%9}, {%0,%1,%2,%3};"
        : "+f"(d[0]), "+f"(d[1]), "+f"(d[2]), "+f"(d[3])
        : "r"(a[0]), "r"(a[1]), "r"(a[2]), "r"(a[3]), "r"(b0), "r"(b1));
}

// Kahan add, rounding-mode-pinned
__device__ __forceinline__ void kadd(float& s, float& c, float t) {
    float y = __fsub_rn(t, c);
    float u = __fadd_rn(s, y);
    c = __fsub_rn(__fsub_rn(u, s), y);
    s = u;
}
// compensated product-accumulate (rescore path)
__device__ __forceinline__ void cdot(float& s, float& c, float& es, float a, float b) {
    float p = __fmul_rn(a, b);
    float e = __fmaf_rn(a, b, -p);
    kadd(s, c, p);
    es = __fadd_rn(es, e);
}

// ---------------- precise q projection: block-compensated accumulation ----------------
__global__ void __launch_bounds__(256)
cproj_kernel(const float* __restrict__ X,
             const float* __restrict__ Wr, const float* __restrict__ Wi,
             const float* __restrict__ br, const float* __restrict__ bi,
             float* __restrict__ Y)
{
    __shared__ float2 Xs[16][64];
    __shared__ float2 Ws[16][64];
    const int tid = threadIdx.x;
    const int m0 = blockIdx.y * 64;
    const int n0 = blockIdx.x * 64;
    const int kk = tid & 15;
    const int rr = tid >> 4;
    const int ty4 = (tid >> 4) * 4;
    const int tx4 = (tid & 15) * 4;

    float cr[4][4], ci[4][4], er[4][4], ei[4][4];
#pragma unroll
    for (int i = 0; i < 4; i++)
#pragma unroll
        for (int j = 0; j < 4; j++) { cr[i][j] = 0.f; ci[i][j] = 0.f; er[i][j] = 0.f; ei[i][j] = 0.f; }

    for (int k0 = 0; k0 < DIM; k0 += 16) {
#pragma unroll
        for (int r = 0; r < 4; r++) {
            int row = rr + r * 16;
            Xs[kk][row] = *(const float2*)&X[((size_t)(m0 + row) * DIM + k0 + kk) * 2];
            float wr = Wr[(size_t)(n0 + row) * DIM + k0 + kk];
            float wi = Wi[(size_t)(n0 + row) * DIM + k0 + kk];
            Ws[kk][row] = make_float2(wr, wi);
        }
        __syncthreads();

        float tr[4][4], ti[4][4];
#pragma unroll
        for (int i = 0; i < 4; i++)
#pragma unroll
            for (int j = 0; j < 4; j++) { tr[i][j] = 0.f; ti[i][j] = 0.f; }

#pragma unroll
        for (int k = 0; k < 16; k++) {
            float2 a[4], w[4];
#pragma unroll
            for (int i = 0; i < 4; i++) a[i] = Xs[k][ty4 + i];
#pragma unroll
            for (int j = 0; j < 4; j++) w[j] = Ws[k][tx4 + j];
#pragma unroll
            for (int i = 0; i < 4; i++)
#pragma unroll
                for (int j = 0; j < 4; j++) {
                    tr[i][j] = __fmaf_rn(a[i].x, w[j].x, tr[i][j]);
                    tr[i][j] = __fmaf_rn(-a[i].y, w[j].y, tr[i][j]);
                    ti[i][j] = __fmaf_rn(a[i].x, w[j].y, ti[i][j]);
                    ti[i][j] = __fmaf_rn(a[i].y, w[j].x, ti[i][j]);
                }
        }
#pragma unroll
        for (int i = 0; i < 4; i++)
#pragma unroll
            for (int j = 0; j < 4; j++) {
                kadd(cr[i][j], er[i][j], tr[i][j]);
                kadd(ci[i][j], ei[i][j], ti[i][j]);
            }
        __syncthreads();
    }
#pragma unroll
    for (int i = 0; i < 4; i++) {
        int m = m0 + ty4 + i;
#pragma unroll
        for (int j = 0; j < 4; j++) {
            int n = n0 + tx4 + j;
            Y[((size_t)m * DIM + n) * 2 + 0] = __fadd_rn(cr[i][j], er[i][j]) + br[n];
            Y[((size_t)m * DIM + n) * 2 + 1] = __fadd_rn(ci[i][j], ei[i][j]) + bi[n];
        }
    }
}

// ---------------- fused prep: double mag + fp32 mag + bf16 conversion ----------------
__global__ void __launch_bounds__(128)
prep_bf16_kernel(const float* __restrict__ X, __nv_bfloat16* __restrict__ Xh,
                 double* __restrict__ out_d, float* __restrict__ out_f)
{
    __shared__ double sm[128];
    const int row = blockIdx.x;
    const int tid = threadIdx.x;
    const float* p = X + (size_t)row * TWO_D;
    const int base = tid * 8;

    float4 v0 = *(const float4*)(p + base);
    float4 v1 = *(const float4*)(p + base + 4);

    double s = (double)v0.x * v0.x + (double)v0.y * v0.y
             + (double)v0.z * v0.z + (double)v0.w * v0.w
             + (double)v1.x * v1.x + (double)v1.y * v1.y
             + (double)v1.z * v1.z + (double)v1.w * v1.w;

    __nv_bfloat162 b0 = __float22bfloat162_rn(make_float2(v0.x, v0.y));
    __nv_bfloat162 b1 = __float22bfloat162_rn(make_float2(v0.z, v0.w));
    __nv_bfloat162 b2 = __float22bfloat162_rn(make_float2(v1.x, v1.y));
    __nv_bfloat162 b3 = __float22bfloat162_rn(make_float2(v1.z, v1.w));
    uint4 packed;
    packed.x = *(uint32_t*)&b0; packed.y = *(uint32_t*)&b1;
    packed.z = *(uint32_t*)&b2; packed.w = *(uint32_t*)&b3;
    *(uint4*)(Xh + (size_t)row * TWO_D + base) = packed;

    sm[tid] = s;
    __syncthreads();
    for (int o = 64; o > 0; o >>= 1) {
        if (tid < o) sm[tid] += sm[tid + o];
        __syncthreads();
    }
    if (tid == 0) {
        double m = sqrt(sm[0] + 1e-8);
        out_d[row] = m;
        out_f[row] = (float)m;
    }
}

// ---------------- stage loader (A tile + B tile) ----------------
__device__ __forceinline__ void gemm_load_stage(
    const char* Abase, const char* Bbase, size_t rstride,
    uint32_t sb, int tid, int it, int s)
{
    const int seg = tid & 7;
    const size_t koff = (size_t)it * 128 + (size_t)seg * 16;
    const uint32_t so = sb + (uint32_t)s * STAGE_BYTES;
#pragma unroll
    for (int j = 0; j < 4; j++) {
        int row = (tid >> 3) + 32 * j;
        cpasync16(so + row * 144 + seg * 16, Abase + (size_t)row * rstride + koff);
    }
#pragma unroll
    for (int j = 0; j < 4; j++) {
        int row = (tid >> 3) + 32 * j;
        cpasync16(so + TILE_BYTES + row * 144 + seg * 16, Bbase + (size_t)row * rstride + koff);
    }
    asm volatile("cp.async.commit_group;" ::: "memory");
}

// ---------------- coherence GEMM: 3-stage pipeline, x4 B-frag loads ----------------
__global__ void __launch_bounds__(256, 2)
coh_gemm_mma(const __nv_bfloat16* __restrict__ A, const __nv_bfloat16* __restrict__ B,
             const float* __restrict__ qmag, const float* __restrict__ kmag,
             __half* __restrict__ C)
{
    extern __shared__ __align__(16) char smraw[];
    const uint32_t sb = smem_u32(smraw);
    const int tid = threadIdx.x;
    const int wid = tid >> 5, lane = tid & 31;
    const int m0 = blockIdx.x * GTM;
    const int n0 = blockIdx.y * GTN;
    const int wm0 = (wid & 1) * 64, wn0 = (wid >> 1) * 32;

    float acc[4][4][4];
#pragma unroll
    for (int a = 0; a < 4; a++)
#pragma unroll
        for (int b = 0; b < 4; b++)
#pragma unroll
            for (int c = 0; c < 4; c++) acc[a][b][c] = 0.f;

    const char* Abase = (const char*)A + (size_t)m0 * 2048;
    const char* Bbase = (const char*)B + (size_t)n0 * 2048;

    gemm_load_stage(Abase, Bbase, 2048, sb, tid, 0, 0);
    gemm_load_stage(Abase, Bbase, 2048, sb, tid, 1, 1);

    const int frow = lane & 15, fcol = (lane >> 4) * 8;
    int buf = 0;

    for (int it = 0; it < KCHUNKS; it++) {
        if (it < KCHUNKS - 1) {
            asm volatile("cp.async.wait_group 1;" ::: "memory");
        } else {
            asm volatile("cp.async.wait_group 0;" ::: "memory");
        }
        __syncthreads();
        if (it + 2 < KCHUNKS)
            gemm_load_stage(Abase, Bbase, 2048, sb, tid, it + 2, (it + 2) % NSTG);

        const uint32_t aB = sb + (uint32_t)buf * STAGE_BYTES;
        const uint32_t bB = aB + TILE_BYTES;
#pragma unroll
        for (int ks = 0; ks < 4; ks++) {
            uint32_t afr[4][4], bfr[2][4];
#pragma unroll
            for (int fm = 0; fm < 4; fm++)
                ldmx4(afr[fm], aB + (wm0 + fm * 16 + frow) * 144 + (ks * 16 + fcol) * 2);
#pragma unroll
            for (int g = 0; g < 2; g++)
                ldmx4(bfr[g], bB + (wn0 + g * 16 + frow) * 144 + (ks * 16 + fcol) * 2);
#pragma unroll
            for (int fm = 0; fm < 4; fm++)
#pragma unroll
                for (int fn = 0; fn < 4; fn++) {
                    const int g = fn >> 1, hf = fn & 1;
                    mma_bf16_b2(acc[fm][fn], afr[fm], bfr[g][hf], bfr[g][hf + 2]);
                }
        }
        buf = (buf + 1) % NSTG;
    }

#pragma unroll
    for (int fm = 0; fm < 4; fm++) {
        int mlo = m0 + wm0 + fm * 16 + (lane >> 2);
        int mhi = mlo + 8;
        float qlo = qmag[mlo], qhi = qmag[mhi];
#pragma unroll
        for (int fn = 0; fn < 4; fn++) {
            int n = n0 + wn0 + fn * 8 + (lane & 3) * 2;
            float k0v = kmag[n], k1v = kmag[n + 1];
            __half2 hlo, hhi;
            hlo.x = __float2half_rn(acc[fm][fn][0] / (qlo * k0v + EPSF));
            hlo.y = __float2half_rn(acc[fm][fn][1] / (qlo * k1v + EPSF));
            hhi.x = __float2half_rn(acc[fm][fn][2] / (qhi * k0v + EPSF));
            hhi.y = __float2half_rn(acc[fm][fn][3] / (qhi * k1v + EPSF));
            *(__half2*)&C[(size_t)mlo * NKEYS + n] = hlo;
            *(__half2*)&C[(size_t)mhi * NKEYS + n] = hhi;
        }
    }
}

// ------- top-64: smem-cached row, single global pass + rescore + softmax + gather + norm ----
__global__ void __launch_bounds__(256)
topk_kernel(const __half* __restrict__ scores,
            const float* __restrict__ qbuf,
            const float* __restrict__ keys,
            const double* __restrict__ qmagd,
            const double* __restrict__ kmagd,
            const float* __restrict__ values,
            const float* __restrict__ gamma,
            float* __restrict__ outn)
{
    extern __shared__ __align__(16) char tks[];
    __half2* sh_row2 = (__half2*)(tks + TK_ROW);
    int*     hist    = (int*)(tks + TK_HIST);
    float*   qs      = (float*)(tks + TK_QS);
    double*  cand_d  = (double*)(tks + TK_CANDD);
    int*     cand_i  = (int*)(tks + TK_CANDI);

    __shared__ int    csum[256];
    __shared__ int    s_cnt;
    __shared__ int    s_thresh;
    __shared__ double sel_d[TOPK];
    __shared__ int    sel_i[TOPK];
    __shared__ float  s_w[TOPK];
    __shared__ double redv[8];
    __shared__ int    redi[8];
    __shared__ float  snorm[256];
    __shared__ float  s_inv;

    const int q = blockIdx.x;
    const int tid = threadIdx.x;
    const __half2* row2 = (const __half2*)(scores + (size_t)q * NKEYS);

    for (int i = tid; i < NBINS; i += 256) hist[i] = 0;
    for (int i = tid; i < TWO_D; i += 256) qs[i] = qbuf[(size_t)q * TWO_D + i];
    if (tid == 0) s_cnt = 0;
    __syncthreads();

    // pass 1: global read -> smem cache + histogram
    for (int i = tid; i < NKEYS / 2; i += 256) {
        __half2 h2 = row2[i];
        sh_row2[i] = h2;
        float2 s2 = __half22float2(h2);
        int b0 = (int)floorf(__fmaf_rn(s2.x, 1024.f, 1024.f));
        int b1 = (int)floorf(__fmaf_rn(s2.y, 1024.f, 1024.f));
        b0 = max(0, min(NBINS - 1, b0));
        b1 = max(0, min(NBINS - 1, b1));
        atomicAdd(&hist[b0], 1);
        atomicAdd(&hist[b1], 1);
    }
    __syncthreads();

    {
        int c = 0;
#pragma unroll
        for (int j = 0; j < 8; j++) c += hist[tid * 8 + j];
        csum[tid] = c;
    }
    __syncthreads();
    if (tid == 0) {
        int acc = 0, thr = 0;
        for (int ch = 255; ch >= 0; ch--) {
            if (acc + csum[ch] >= TOPK) {
                for (int b = ch * 8 + 7; b >= ch * 8; b--) {
                    acc += hist[b];
                    if (acc >= TOPK) { thr = b; break; }
                }
                break;
            }
            acc += csum[ch];
        }
        s_thresh = max(thr - 2, 0);   // 2-bin margin (1.95e-3) >> bf16 screen + half store error
    }
    __syncthreads();
    const int thresh = s_thresh;

    // pass 2: candidate collection from smem cache
    for (int i = tid; i < NKEYS / 2; i += 256) {
        float2 s2 = __half22float2(sh_row2[i]);
        int b0 = (int)floorf(__fmaf_rn(s2.x, 1024.f, 1024.f));
        int b1 = (int)floorf(__fmaf_rn(s2.y, 1024.f, 1024.f));
        b0 = max(0, min(NBINS - 1, b0));
        b1 = max(0, min(NBINS - 1, b1));
        if (b0 >= thresh) {
            int pos = atomicAdd(&s_cnt, 1);
            if (pos < CAP) cand_i[pos] = 2 * i;
        }
        if (b1 >= thresh) {
            int pos = atomicAdd(&s_cnt, 1);
            if (pos < CAP) cand_i[pos] = 2 * i + 1;
        }
    }
    __syncthreads();
    const int cnt = min(s_cnt, CAP);

    // ---- float-float compensated rescore (one warp per candidate) ----
    {
        const int wid = tid >> 5, lane = tid & 31;
        const double qm = qmagd[q];
        for (int c = wid; c < cnt; c += 8) {
            const int ki = cand_i[c];
            const float* kr = keys + (size_t)ki * TWO_D;
            float s = 0.f, comp = 0.f, es = 0.f;
#pragma unroll
            for (int t = 0; t < 8; t++) {
                int e = t * 128 + lane * 4;
                float4 kv = *(const float4*)(kr + e);
                cdot(s, comp, es, qs[e],     kv.x);
                cdot(s, comp, es, qs[e + 1], kv.y);
                cdot(s, comp, es, qs[e + 2], kv.z);
                cdot(s, comp, es, qs[e + 3], kv.w);
            }
            double acc = (double)s + (double)comp + (double)es;
#pragma unroll
            for (int o = 16; o > 0; o >>= 1)
                acc += __shfl_down_sync(0xffffffffu, acc, o);
            if (lane == 0) cand_d[c] = acc / (qm * kmagd[ki] + (double)EPSF);
        }
    }
    __syncthreads();

    for (int t = 0; t < TOPK; t++) {
        double bv = -1e300; int bi = 0;
        for (int i = tid; i < cnt; i += 256) {
            double v = cand_d[i];
            if (v > bv) { bv = v; bi = i; }
        }
#pragma unroll
        for (int o = 16; o > 0; o >>= 1) {
            double ov = __shfl_down_sync(0xffffffffu, bv, o);
            int    oi = __shfl_down_sync(0xffffffffu, bi, o);
            if (ov > bv) { bv = ov; bi = oi; }
        }
        if ((tid & 31) == 0) { redv[tid >> 5] = bv; redi[tid >> 5] = bi; }
        __syncthreads();
        if (tid == 0) {
            double fv = redv[0]; int fi = redi[0];
#pragma unroll
            for (int w = 1; w < 8; w++)
                if (redv[w] > fv) { fv = redv[w]; fi = redi[w]; }
            sel_d[t] = fv; sel_i[t] = cand_i[fi];
            cand_d[fi] = -1e300;
        }
        __syncthreads();
    }

    if (tid == 0) {
        float m = (float)sel_d[0];
        float z = 0.f;
        for (int t = 0; t < TOPK; t++) { float w = expf((float)sel_d[t] - m); s_w[t] = w; z += w; }
        float inv = 1.0f / z;
        for (int t = 0; t < TOPK; t++) s_w[t] *= inv;
    }
    __syncthreads();

    const int col = tid * 4;
    float4 acc = make_float4(0.f, 0.f, 0.f, 0.f);
    for (int t = 0; t < TOPK; t++) {
        const float4 v = *(const float4*)&values[(size_t)sel_i[t] * TWO_D + col];
        float w = s_w[t];
        acc.x += w * v.x; acc.y += w * v.y; acc.z += w * v.z; acc.w += w * v.w;
    }

    snorm[tid] = acc.x * acc.x + acc.y * acc.y + acc.z * acc.z + acc.w * acc.w;
    __syncthreads();
    for (int o = 128; o > 0; o >>= 1) {
        if (tid < o) snorm[tid] += snorm[tid + o];
        __syncthreads();
    }
    if (tid == 0) {
        float mean = snorm[0] / (float)DIM;
        s_inv = 1.0f / sqrtf(mean + EPSF);
    }
    __syncthreads();
    const float inv = s_inv;
    float2 g2 = *(const float2*)&gamma[col >> 1];
    float4 o4;
    o4.x = acc.x * g2.x * inv;
    o4.y = acc.y * g2.x * inv;
    o4.z = acc.z * g2.y * inv;
    o4.w = acc.w * g2.y * inv;
    *(float4*)&outn[(size_t)q * TWO_D + col] = o4;
}

// ---------------- split preps (out-projection) ----------------
__global__ void __launch_bounds__(256)
prep_splitAo_kernel(const float* __restrict__ X, __nv_bfloat16* __restrict__ A2)
{
    const int row = blockIdx.x;
    const int base = threadIdx.x * 4;
    float4 v = *(const float4*)&X[(size_t)row * TWO_D + base];
    __nv_bfloat16 h0 = __float2bfloat16(v.x), h1 = __float2bfloat16(v.y);
    __nv_bfloat16 h2 = __float2bfloat16(v.z), h3 = __float2bfloat16(v.w);
    __nv_bfloat16 l0 = __float2bfloat16(v.x - __bfloat162float(h0));
    __nv_bfloat16 l1 = __float2bfloat16(v.y - __bfloat162float(h1));
    __nv_bfloat16 l2 = __float2bfloat16(v.z - __bfloat162float(h2));
    __nv_bfloat16 l3 = __float2bfloat16(v.w - __bfloat162float(h3));
    __nv_bfloat16* r = A2 + (size_t)row * PKO;
    uint2 hp, lp;
    ((__nv_bfloat16*)&hp)[0] = h0; ((__nv_bfloat16*)&hp)[1] = h1;
    ((__nv_bfloat16*)&hp)[2] = h2; ((__nv_bfloat16*)&hp)[3] = h3;
    ((__nv_bfloat16*)&lp)[0] = l0; ((__nv_bfloat16*)&lp)[1] = l1;
    ((__nv_bfloat16*)&lp)[2] = l2; ((__nv_bfloat16*)&lp)[3] = l3;
    *(uint2*)(r + base)          = hp;
    *(uint2*)(r + TWO_D + base)  = hp;
    *(uint2*)(r + 2048 + base)   = lp;
}

__global__ void __launch_bounds__(256)
prep_splitBo_kernel(const float* __restrict__ Wr, const float* __restrict__ Wi,
                    __nv_bfloat16* __restrict__ B2)
{
    const int j = blockIdx.x;
    const int n = j >> 1, s = j & 1;
    __nv_bfloat16* r = B2 + (size_t)j * PKO;
    for (int c = threadIdx.x; c < TWO_D; c += 256) {
        int d = c >> 1, p = c & 1;
        float v;
        if (s == 0) v = (p == 0) ? Wr[(size_t)n * DIM + d] : -Wi[(size_t)n * DIM + d];
        else        v = (p == 0) ? Wi[(size_t)n * DIM + d] :  Wr[(size_t)n * DIM + d];
        __nv_bfloat16 h = __float2bfloat16(v);
        __nv_bfloat16 l = __float2bfloat16(v - __bfloat162float(h));
        r[c] = h;
        r[TWO_D + c] = l;
        r[2048 + c] = h;
    }
}

// ---------------- out-projection GEMM (split-bf16, K=3072, x4 B-frag loads) -------------
__global__ void __launch_bounds__(256, 2)
proj_gemm_mma(const __nv_bfloat16* __restrict__ A, const __nv_bfloat16* __restrict__ B,
              const float* __restrict__ br, const float* __restrict__ bi,
              float* __restrict__ C, int kchunks)
{
    extern __shared__ __align__(16) char smraw[];
    const uint32_t sb = smem_u32(smraw);
    const int tid = threadIdx.x;
    const int wid = tid >> 5, lane = tid & 31;
    const int m0 = blockIdx.x * 128;
    const int n0 = blockIdx.y * 128;
    const int wm0 = (wid & 1) * 64, wn0 = (wid >> 1) * 32;
    const size_t rstride = (size_t)kchunks * 128;

    float acc[4][4][4];
#pragma unroll
    for (int a = 0; a < 4; a++)
#pragma unroll
        for (int b = 0; b < 4; b++)
#pragma unroll
            for (int c = 0; c < 4; c++) acc[a][b][c] = 0.f;

    const char* Abase = (const char*)A + (size_t)m0 * rstride;
    const char* Bbase = (const char*)B + (size_t)n0 * rstride;

    gemm_load_stage(Abase, Bbase, rstride, sb, tid, 0, 0);
    int buf = 0;
    const int frow = lane & 15, fcol = (lane >> 4) * 8;

    for (int it = 0; it < kchunks; it++) {
        if (it < kchunks - 1) {
            gemm_load_stage(Abase, Bbase, rstride, sb, tid, it + 1, buf ^ 1);
            asm volatile("cp.async.wait_group 1;" ::: "memory");
        } else {
            asm volatile("cp.async.wait_group 0;" ::: "memory");
        }
        __syncthreads();
        const uint32_t aB = sb + (uint32_t)buf * STAGE_BYTES;
        const uint32_t bB = aB + TILE_BYTES;
#pragma unroll
        for (int ks = 0; ks < 4; ks++) {
            uint32_t afr[4][4], bfr[2][4];
#pragma unroll
            for (int fm = 0; fm < 4; fm++)
                ldmx4(afr[fm], aB + (wm0 + fm * 16 + frow) * 144 + (ks * 16 + fcol) * 2);
#pragma unroll
            for (int g = 0; g < 2; g++)
                ldmx4(bfr[g], bB + (wn0 + g * 16 + frow) * 144 + (ks * 16 + fcol) * 2);
#pragma unroll
            for (int fm = 0; fm < 4; fm++)
#pragma unroll
                for (int fn = 0; fn < 4; fn++) {
                    const int g = fn >> 1, hf = fn & 1;
                    mma_bf16_b2(acc[fm][fn], afr[fm], bfr[g][hf], bfr[g][hf + 2]);
                }
        }
        __syncthreads();
        buf ^= 1;
    }

#pragma unroll
    for (int fm = 0; fm < 4; fm++) {
        int mlo = m0 + wm0 + fm * 16 + (lane >> 2);
        int mhi = mlo + 8;
#pragma unroll
        for (int fn = 0; fn < 4; fn++) {
            int n = n0 + wn0 + fn * 8 + (lane & 3) * 2;
            float b0 = br[n >> 1], b1 = bi[n >> 1];
            float2 vlo = make_float2(acc[fm][fn][0] + b0, acc[fm][fn][1] + b1);
            float2 vhi = make_float2(acc[fm][fn][2] + b0, acc[fm][fn][3] + b1);
            *(float2*)&C[(size_t)mlo * TWO_D + n] = vlo;
            *(float2*)&C[(size_t)mhi * TWO_D + n] = vhi;
        }
    }
}

// ---------------- launch ----------------
extern "C" void kernel_launch(void* const* d_in, const int* in_sizes, int n_in,
                              void* d_out, int out_size)
{
    const float* query = (const float*)d_in[0];
    const float* keys  = (const float*)d_in[1];
    const float* vals  = (const float*)d_in[2];
    const float* Wq_r  = (const float*)d_in[3];
    const float* Wq_i  = (const float*)d_in[4];
    const float* bq_r  = (const float*)d_in[5];
    const float* bq_i  = (const float*)d_in[6];
    const float* Wo_r  = (const float*)d_in[7];
    const float* Wo_i  = (const float*)d_in[8];
    const float* bo_r  = (const float*)d_in[9];
    const float* bo_i  = (const float*)d_in[10];
    const float* gamma = (const float*)d_in[11];
    float* out = (float*)d_out;

    void *p_q, *p_qh, *p_kh, *p_qmd, *p_qmf, *p_kmd, *p_kmf, *p_sc, *p_nrm, *p_A2o, *p_B2o;
    cudaGetSymbolAddress(&p_q,   g_q);
    cudaGetSymbolAddress(&p_qh,  g_qh);
    cudaGetSymbolAddress(&p_kh,  g_kh);
    cudaGetSymbolAddress(&p_qmd, g_qmagd);
    cudaGetSymbolAddress(&p_qmf, g_qmagf);
    cudaGetSymbolAddress(&p_kmd, g_kmagd);
    cudaGetSymbolAddress(&p_kmf, g_kmagf);
    cudaGetSymbolAddress(&p_sc,  g_scoresh);
    cudaGetSymbolAddress(&p_nrm, g_norm);
    cudaGetSymbolAddress(&p_A2o, g_A2o);
    cudaGetSymbolAddress(&p_B2o, g_B2o);
    float*  qbuf  = (float*)p_q;
    __nv_bfloat16* qh = (__nv_bfloat16*)p_qh;
    __nv_bfloat16* kh = (__nv_bfloat16*)p_kh;
    double* qmagd = (double*)p_qmd;
    float*  qmagf = (float*)p_qmf;
    double* kmagd = (double*)p_kmd;
    float*  kmagf = (float*)p_kmf;
    __half* sc    = (__half*)p_sc;
    float*  nrmb  = (float*)p_nrm;
    __nv_bfloat16* A2o = (__nv_bfloat16*)p_A2o;
    __nv_bfloat16* B2o = (__nv_bfloat16*)p_B2o;

    cudaFuncSetAttribute(coh_gemm_mma, cudaFuncAttributeMaxDynamicSharedMemorySize, GEMM_SMEM);
    cudaFuncSetAttribute(proj_gemm_mma, cudaFuncAttributeMaxDynamicSharedMemorySize, PGEMM_SMEM);
    cudaFuncSetAttribute(topk_kernel, cudaFuncAttributeMaxDynamicSharedMemorySize, TK_SMEM);

    dim3 gproj(DIM / 64, QROWS / 64);

    prep_bf16_kernel<<<NKEYS, 128>>>(keys, kh, kmagd, kmagf);
    prep_splitBo_kernel<<<TWO_D, 256>>>(Wo_r, Wo_i, B2o);

    // precise q projection (block-compensated Kahan, fma pipe)
    cproj_kernel<<<gproj, 256>>>(query, Wq_r, Wq_i, bq_r, bq_i, qbuf);
    prep_bf16_kernel<<<QROWS, 128>>>(qbuf, qh, qmagd, qmagf);

    // coherence screening GEMM
    dim3 ggemm(QROWS / GTM, NKEYS / GTN);
    coh_gemm_mma<<<ggemm, 256, GEMM_SMEM>>>(qh, kh, qmagf, kmagf, sc);

    // top-64 + softmax + gather + phase norm (smem-cached row)
    topk_kernel<<<QROWS, 256, TK_SMEM>>>(sc, qbuf, keys, qmagd, kmagd, vals, gamma, nrmb);

    // output projection (tensor, 3-term split, K=3072)
    prep_splitAo_kernel<<<QROWS, 256>>>(nrmb, A2o);
    dim3 gpro(QROWS / 128, TWO_D / 128);
    proj_gemm_mma<<<gpro, 256, PGEMM_SMEM>>>(A2o, B2o, bo_r, bo_i, out, PKO / 64);
}

// round 16
// speedup vs baseline: 1.2786x; 1.2786x over previous
#include <cuda_runtime.h>
#include <cuda_fp16.h>
#include <cuda_bf16.h>
#include <math.h>
#include <stdint.h>

#define QROWS 4096
#define DIM   512
#define TWO_D 1024
#define NKEYS 32768
#define TOPK  64
#define EPSF  1e-8f
#define NBINS 2048
#define CAP   1024

// ---- coherence GEMM: 128x128 tile, 3-stage cp.async ----
#define GTM 128
#define GTN 128
#define TILE_BYTES (128 * 144)
#define STAGE_BYTES (2 * TILE_BYTES)        // 36864
#define NSTG 3
#define GEMM_SMEM (NSTG * STAGE_BYTES)      // 110592
#define KCHUNKS 16

// ---- out-projection split-bf16 GEMM: K = 3072 ----
#define PKO 3072
#define PGEMM_SMEM (2 * STAGE_BYTES)        // 73728, 2-stage

// ---------------- scratch (no allocations allowed) ----------------
__device__ float  g_q[(size_t)QROWS * TWO_D];
__device__ __nv_bfloat16 g_qh[(size_t)QROWS * TWO_D];
__device__ __nv_bfloat16 g_kh[(size_t)NKEYS * TWO_D];
__device__ double g_qmagd[QROWS];
__device__ float  g_qmagf[QROWS];
__device__ double g_kmagd[NKEYS];
__device__ float  g_kmagf[NKEYS];
__device__ __half g_scoresh[(size_t)QROWS * NKEYS];
__device__ float  g_norm[(size_t)QROWS * TWO_D];
__device__ __nv_bfloat16 g_A2o[(size_t)QROWS * PKO];
__device__ __nv_bfloat16 g_B2o[(size_t)TWO_D * PKO];

// ---------------- helpers ----------------
__device__ __forceinline__ uint32_t smem_u32(const void* p) {
    uint32_t a;
    asm("{ .reg .u64 t; cvta.to.shared.u64 t, %1; cvt.u32.u64 %0, t; }" : "=r"(a) : "l"(p));
    return a;
}
__device__ __forceinline__ void cpasync16(uint32_t dst, const void* src) {
    asm volatile("cp.async.cg.shared.global [%0], [%1], 16;" :: "r"(dst), "l"(src) : "memory");
}
__device__ __forceinline__ void ldmx4(uint32_t* r, uint32_t a) {
    asm volatile("ldmatrix.sync.aligned.m8n8.x4.shared.b16 {%0,%1,%2,%3}, [%4];"
                 : "=r"(r[0]), "=r"(r[1]), "=r"(r[2]), "=r"(r[3]) : "r"(a));
}
__device__ __forceinline__ void mma_bf16_b2(float* d, const uint32_t* a, uint32_t b0, uint32_t b1) {
    asm volatile(
        "mma.sync.aligned.m16n8k16.row.col.f32.bf16.bf16.f32 "
        "{%0,%1,%2,%3}, {%4,%5,%6,%7}, {%8,%9}, {%0,%1,%2,%3};"
        : "+f"(d[0]), "+f"(d[1]), "+f"(d[2]), "+f"(d[3])
        : "r"(a[0]), "r"(a[1]), "r"(a[2]), "r"(a[3]), "r"(b0), "r"(b1));
}

// Kahan add, rounding-mode-pinned
__device__ __forceinline__ void kadd(float& s, float& c, float t) {
    float y = __fsub_rn(t, c);
    float u = __fadd_rn(s, y);
    c = __fsub_rn(__fsub_rn(u, s), y);
    s = u;
}
// compensated product-accumulate (rescore path)
__device__ __forceinline__ void cdot(float& s, float& c, float& es, float a, float b) {
    float p = __fmul_rn(a, b);
    float e = __fmaf_rn(a, b, -p);
    kadd(s, c, p);
    es = __fadd_rn(es, e);
}

// ---------------- precise q projection: block-compensated accumulation ----------------
__global__ void __launch_bounds__(256)
cproj_kernel(const float* __restrict__ X,
             const float* __restrict__ Wr, const float* __restrict__ Wi,
             const float* __restrict__ br, const float* __restrict__ bi,
             float* __restrict__ Y)
{
    __shared__ float2 Xs[16][64];
    __shared__ float2 Ws[16][64];
    const int tid = threadIdx.x;
    const int m0 = blockIdx.y * 64;
    const int n0 = blockIdx.x * 64;
    const int kk = tid & 15;
    const int rr = tid >> 4;
    const int ty4 = (tid >> 4) * 4;
    const int tx4 = (tid & 15) * 4;

    float cr[4][4], ci[4][4], er[4][4], ei[4][4];
#pragma unroll
    for (int i = 0; i < 4; i++)
#pragma unroll
        for (int j = 0; j < 4; j++) { cr[i][j] = 0.f; ci[i][j] = 0.f; er[i][j] = 0.f; ei[i][j] = 0.f; }

    for (int k0 = 0; k0 < DIM; k0 += 16) {
#pragma unroll
        for (int r = 0; r < 4; r++) {
            int row = rr + r * 16;
            Xs[kk][row] = *(const float2*)&X[((size_t)(m0 + row) * DIM + k0 + kk) * 2];
            float wr = Wr[(size_t)(n0 + row) * DIM + k0 + kk];
            float wi = Wi[(size_t)(n0 + row) * DIM + k0 + kk];
            Ws[kk][row] = make_float2(wr, wi);
        }
        __syncthreads();

        float tr[4][4], ti[4][4];
#pragma unroll
        for (int i = 0; i < 4; i++)
#pragma unroll
            for (int j = 0; j < 4; j++) { tr[i][j] = 0.f; ti[i][j] = 0.f; }

#pragma unroll
        for (int k = 0; k < 16; k++) {
            float2 a[4], w[4];
#pragma unroll
            for (int i = 0; i < 4; i++) a[i] = Xs[k][ty4 + i];
#pragma unroll
            for (int j = 0; j < 4; j++) w[j] = Ws[k][tx4 + j];
#pragma unroll
            for (int i = 0; i < 4; i++)
#pragma unroll
                for (int j = 0; j < 4; j++) {
                    tr[i][j] = __fmaf_rn(a[i].x, w[j].x, tr[i][j]);
                    tr[i][j] = __fmaf_rn(-a[i].y, w[j].y, tr[i][j]);
                    ti[i][j] = __fmaf_rn(a[i].x, w[j].y, ti[i][j]);
                    ti[i][j] = __fmaf_rn(a[i].y, w[j].x, ti[i][j]);
                }
        }
#pragma unroll
        for (int i = 0; i < 4; i++)
#pragma unroll
            for (int j = 0; j < 4; j++) {
                kadd(cr[i][j], er[i][j], tr[i][j]);
                kadd(ci[i][j], ei[i][j], ti[i][j]);
            }
        __syncthreads();
    }
#pragma unroll
    for (int i = 0; i < 4; i++) {
        int m = m0 + ty4 + i;
#pragma unroll
        for (int j = 0; j < 4; j++) {
            int n = n0 + tx4 + j;
            Y[((size_t)m * DIM + n) * 2 + 0] = __fadd_rn(cr[i][j], er[i][j]) + br[n];
            Y[((size_t)m * DIM + n) * 2 + 1] = __fadd_rn(ci[i][j], ei[i][j]) + bi[n];
        }
    }
}

// ---------------- fused prep: double mag + fp32 mag + bf16 conversion ----------------
__global__ void __launch_bounds__(128)
prep_bf16_kernel(const float* __restrict__ X, __nv_bfloat16* __restrict__ Xh,
                 double* __restrict__ out_d, float* __restrict__ out_f)
{
    __shared__ double sm[128];
    const int row = blockIdx.x;
    const int tid = threadIdx.x;
    const float* p = X + (size_t)row * TWO_D;
    const int base = tid * 8;

    float4 v0 = *(const float4*)(p + base);
    float4 v1 = *(const float4*)(p + base + 4);

    double s = (double)v0.x * v0.x + (double)v0.y * v0.y
             + (double)v0.z * v0.z + (double)v0.w * v0.w
             + (double)v1.x * v1.x + (double)v1.y * v1.y
             + (double)v1.z * v1.z + (double)v1.w * v1.w;

    __nv_bfloat162 b0 = __float22bfloat162_rn(make_float2(v0.x, v0.y));
    __nv_bfloat162 b1 = __float22bfloat162_rn(make_float2(v0.z, v0.w));
    __nv_bfloat162 b2 = __float22bfloat162_rn(make_float2(v1.x, v1.y));
    __nv_bfloat162 b3 = __float22bfloat162_rn(make_float2(v1.z, v1.w));
    uint4 packed;
    packed.x = *(uint32_t*)&b0; packed.y = *(uint32_t*)&b1;
    packed.z = *(uint32_t*)&b2; packed.w = *(uint32_t*)&b3;
    *(uint4*)(Xh + (size_t)row * TWO_D + base) = packed;

    sm[tid] = s;
    __syncthreads();
    for (int o = 64; o > 0; o >>= 1) {
        if (tid < o) sm[tid] += sm[tid + o];
        __syncthreads();
    }
    if (tid == 0) {
        double m = sqrt(sm[0] + 1e-8);
        out_d[row] = m;
        out_f[row] = (float)m;
    }
}

// ---------------- stage loader (A tile + B tile) ----------------
__device__ __forceinline__ void gemm_load_stage(
    const char* Abase, const char* Bbase, size_t rstride,
    uint32_t sb, int tid, int it, int s)
{
    const int seg = tid & 7;
    const size_t koff = (size_t)it * 128 + (size_t)seg * 16;
    const uint32_t so = sb + (uint32_t)s * STAGE_BYTES;
#pragma unroll
    for (int j = 0; j < 4; j++) {
        int row = (tid >> 3) + 32 * j;
        cpasync16(so + row * 144 + seg * 16, Abase + (size_t)row * rstride + koff);
    }
#pragma unroll
    for (int j = 0; j < 4; j++) {
        int row = (tid >> 3) + 32 * j;
        cpasync16(so + TILE_BYTES + row * 144 + seg * 16, Bbase + (size_t)row * rstride + koff);
    }
    asm volatile("cp.async.commit_group;" ::: "memory");
}

// ---------------- coherence GEMM: 3-stage pipeline, x4 B-frag loads ----------------
__global__ void __launch_bounds__(256, 2)
coh_gemm_mma(const __nv_bfloat16* __restrict__ A, const __nv_bfloat16* __restrict__ B,
             const float* __restrict__ qmag, const float* __restrict__ kmag,
             __half* __restrict__ C)
{
    extern __shared__ __align__(16) char smraw[];
    const uint32_t sb = smem_u32(smraw);
    const int tid = threadIdx.x;
    const int wid = tid >> 5, lane = tid & 31;
    const int m0 = blockIdx.x * GTM;
    const int n0 = blockIdx.y * GTN;
    const int wm0 = (wid & 1) * 64, wn0 = (wid >> 1) * 32;

    float acc[4][4][4];
#pragma unroll
    for (int a = 0; a < 4; a++)
#pragma unroll
        for (int b = 0; b < 4; b++)
#pragma unroll
            for (int c = 0; c < 4; c++) acc[a][b][c] = 0.f;

    const char* Abase = (const char*)A + (size_t)m0 * 2048;
    const char* Bbase = (const char*)B + (size_t)n0 * 2048;

    gemm_load_stage(Abase, Bbase, 2048, sb, tid, 0, 0);
    gemm_load_stage(Abase, Bbase, 2048, sb, tid, 1, 1);

    const int frow = lane & 15, fcol = (lane >> 4) * 8;
    int buf = 0;

    for (int it = 0; it < KCHUNKS; it++) {
        if (it < KCHUNKS - 1) {
            asm volatile("cp.async.wait_group 1;" ::: "memory");
        } else {
            asm volatile("cp.async.wait_group 0;" ::: "memory");
        }
        __syncthreads();
        if (it + 2 < KCHUNKS)
            gemm_load_stage(Abase, Bbase, 2048, sb, tid, it + 2, (it + 2) % NSTG);

        const uint32_t aB = sb + (uint32_t)buf * STAGE_BYTES;
        const uint32_t bB = aB + TILE_BYTES;
#pragma unroll
        for (int ks = 0; ks < 4; ks++) {
            uint32_t afr[4][4], bfr[2][4];
#pragma unroll
            for (int fm = 0; fm < 4; fm++)
                ldmx4(afr[fm], aB + (wm0 + fm * 16 + frow) * 144 + (ks * 16 + fcol) * 2);
#pragma unroll
            for (int g = 0; g < 2; g++)
                ldmx4(bfr[g], bB + (wn0 + g * 16 + frow) * 144 + (ks * 16 + fcol) * 2);
#pragma unroll
            for (int fm = 0; fm < 4; fm++)
#pragma unroll
                for (int fn = 0; fn < 4; fn++) {
                    const int g = fn >> 1, hf = fn & 1;
                    mma_bf16_b2(acc[fm][fn], afr[fm], bfr[g][hf], bfr[g][hf + 2]);
                }
        }
        buf = (buf + 1) % NSTG;
    }

#pragma unroll
    for (int fm = 0; fm < 4; fm++) {
        int mlo = m0 + wm0 + fm * 16 + (lane >> 2);
        int mhi = mlo + 8;
        float qlo = qmag[mlo], qhi = qmag[mhi];
#pragma unroll
        for (int fn = 0; fn < 4; fn++) {
            int n = n0 + wn0 + fn * 8 + (lane & 3) * 2;
            float k0v = kmag[n], k1v = kmag[n + 1];
            __half2 hlo, hhi;
            hlo.x = __float2half_rn(acc[fm][fn][0] / (qlo * k0v + EPSF));
            hlo.y = __float2half_rn(acc[fm][fn][1] / (qlo * k1v + EPSF));
            hhi.x = __float2half_rn(acc[fm][fn][2] / (qhi * k0v + EPSF));
            hhi.y = __float2half_rn(acc[fm][fn][3] / (qhi * k1v + EPSF));
            *(__half2*)&C[(size_t)mlo * NKEYS + n] = hlo;
            *(__half2*)&C[(size_t)mhi * NKEYS + n] = hhi;
        }
    }
}

// ------- top-64 (half2 screen -> float-float rescore -> select) + softmax + gather + norm -----
__global__ void __launch_bounds__(256)
topk_kernel(const __half* __restrict__ scores,
            const float* __restrict__ qbuf,
            const float* __restrict__ keys,
            const double* __restrict__ qmagd,
            const double* __restrict__ kmagd,
            const float* __restrict__ values,
            const float* __restrict__ gamma,
            float* __restrict__ outn)
{
    __shared__ int    hist[NBINS];
    __shared__ int    csum[256];
    __shared__ float  qs[TWO_D];
    __shared__ double cand_d[CAP];
    __shared__ int    cand_i[CAP];
    __shared__ int    s_cnt;
    __shared__ int    s_thresh;
    __shared__ double sel_d[TOPK];
    __shared__ int    sel_i[TOPK];
    __shared__ float  s_w[TOPK];
    __shared__ double redv[8];
    __shared__ int    redi[8];
    __shared__ float  snorm[256];
    __shared__ float  s_inv;

    const int q = blockIdx.x;
    const int tid = threadIdx.x;
    const __half2* row2 = (const __half2*)(scores + (size_t)q * NKEYS);

    for (int i = tid; i < NBINS; i += 256) hist[i] = 0;
    for (int i = tid; i < TWO_D; i += 256) qs[i] = qbuf[(size_t)q * TWO_D + i];
    if (tid == 0) s_cnt = 0;
    __syncthreads();

    for (int i = tid; i < NKEYS / 2; i += 256) {
        float2 s2 = __half22float2(row2[i]);
        int b0 = (int)floorf(__fmaf_rn(s2.x, 1024.f, 1024.f));
        int b1 = (int)floorf(__fmaf_rn(s2.y, 1024.f, 1024.f));
        b0 = max(0, min(NBINS - 1, b0));
        b1 = max(0, min(NBINS - 1, b1));
        atomicAdd(&hist[b0], 1);
        atomicAdd(&hist[b1], 1);
    }
    __syncthreads();

    {
        int c = 0;
#pragma unroll
        for (int j = 0; j < 8; j++) c += hist[tid * 8 + j];
        csum[tid] = c;
    }
    __syncthreads();
    if (tid == 0) {
        int acc = 0, thr = 0;
        for (int ch = 255; ch >= 0; ch--) {
            if (acc + csum[ch] >= TOPK) {
                for (int b = ch * 8 + 7; b >= ch * 8; b--) {
                    acc += hist[b];
                    if (acc >= TOPK) { thr = b; break; }
                }
                break;
            }
            acc += csum[ch];
        }
        s_thresh = max(thr - 2, 0);
    }
    __syncthreads();
    const int thresh = s_thresh;

    for (int i = tid; i < NKEYS / 2; i += 256) {
        float2 s2 = __half22float2(row2[i]);
        int b0 = (int)floorf(__fmaf_rn(s2.x, 1024.f, 1024.f));
        int b1 = (int)floorf(__fmaf_rn(s2.y, 1024.f, 1024.f));
        b0 = max(0, min(NBINS - 1, b0));
        b1 = max(0, min(NBINS - 1, b1));
        if (b0 >= thresh) {
            int pos = atomicAdd(&s_cnt, 1);
            if (pos < CAP) cand_i[pos] = 2 * i;
        }
        if (b1 >= thresh) {
            int pos = atomicAdd(&s_cnt, 1);
            if (pos < CAP) cand_i[pos] = 2 * i + 1;
        }
    }
    __syncthreads();
    const int cnt = min(s_cnt, CAP);

    {
        const int wid = tid >> 5, lane = tid & 31;
        const double qm = qmagd[q];
        for (int c = wid; c < cnt; c += 8) {
            const int ki = cand_i[c];
            const float* kr = keys + (size_t)ki * TWO_D;
            float s = 0.f, comp = 0.f, es = 0.f;
#pragma unroll
            for (int t = 0; t < 8; t++) {
                int e = t * 128 + lane * 4;
                float4 kv = *(const float4*)(kr + e);
                cdot(s, comp, es, qs[e],     kv.x);
                cdot(s, comp, es, qs[e + 1], kv.y);
                cdot(s, comp, es, qs[e + 2], kv.z);
                cdot(s, comp, es, qs[e + 3], kv.w);
            }
            double acc = (double)s + (double)comp + (double)es;
#pragma unroll
            for (int o = 16; o > 0; o >>= 1)
                acc += __shfl_down_sync(0xffffffffu, acc, o);
            if (lane == 0) cand_d[c] = acc / (qm * kmagd[ki] + (double)EPSF);
        }
    }
    __syncthreads();

    for (int t = 0; t < TOPK; t++) {
        double bv = -1e300; int bi = 0;
        for (int i = tid; i < cnt; i += 256) {
            double v = cand_d[i];
            if (v > bv) { bv = v; bi = i; }
        }
#pragma unroll
        for (int o = 16; o > 0; o >>= 1) {
            double ov = __shfl_down_sync(0xffffffffu, bv, o);
            int    oi = __shfl_down_sync(0xffffffffu, bi, o);
            if (ov > bv) { bv = ov; bi = oi; }
        }
        if ((tid & 31) == 0) { redv[tid >> 5] = bv; redi[tid >> 5] = bi; }
        __syncthreads();
        if (tid == 0) {
            double fv = redv[0]; int fi = redi[0];
#pragma unroll
            for (int w = 1; w < 8; w++)
                if (redv[w] > fv) { fv = redv[w]; fi = redi[w]; }
            sel_d[t] = fv; sel_i[t] = cand_i[fi];
            cand_d[fi] = -1e300;
        }
        __syncthreads();
    }

    if (tid == 0) {
        float m = (float)sel_d[0];
        float z = 0.f;
        for (int t = 0; t < TOPK; t++) { float w = expf((float)sel_d[t] - m); s_w[t] = w; z += w; }
        float inv = 1.0f / z;
        for (int t = 0; t < TOPK; t++) s_w[t] *= inv;
    }
    __syncthreads();

    const int col = tid * 4;
    float4 acc = make_float4(0.f, 0.f, 0.f, 0.f);
    for (int t = 0; t < TOPK; t++) {
        const float4 v = *(const float4*)&values[(size_t)sel_i[t] * TWO_D + col];
        float w = s_w[t];
        acc.x += w * v.x; acc.y += w * v.y; acc.z += w * v.z; acc.w += w * v.w;
    }

    snorm[tid] = acc.x * acc.x + acc.y * acc.y + acc.z * acc.z + acc.w * acc.w;
    __syncthreads();
    for (int o = 128; o > 0; o >>= 1) {
        if (tid < o) snorm[tid] += snorm[tid + o];
        __syncthreads();
    }
    if (tid == 0) {
        float mean = snorm[0] / (float)DIM;
        s_inv = 1.0f / sqrtf(mean + EPSF);
    }
    __syncthreads();
    const float inv = s_inv;
    float2 g2 = *(const float2*)&gamma[col >> 1];
    float4 o4;
    o4.x = acc.x * g2.x * inv;
    o4.y = acc.y * g2.x * inv;
    o4.z = acc.z * g2.y * inv;
    o4.w = acc.w * g2.y * inv;
    *(float4*)&outn[(size_t)q * TWO_D + col] = o4;
}

// ---------------- split preps (out-projection) ----------------
__global__ void __launch_bounds__(256)
prep_splitAo_kernel(const float* __restrict__ X, __nv_bfloat16* __restrict__ A2)
{
    const int row = blockIdx.x;
    const int base = threadIdx.x * 4;
    float4 v = *(const float4*)&X[(size_t)row * TWO_D + base];
    __nv_bfloat16 h0 = __float2bfloat16(v.x), h1 = __float2bfloat16(v.y);
    __nv_bfloat16 h2 = __float2bfloat16(v.z), h3 = __float2bfloat16(v.w);
    __nv_bfloat16 l0 = __float2bfloat16(v.x - __bfloat162float(h0));
    __nv_bfloat16 l1 = __float2bfloat16(v.y - __bfloat162float(h1));
    __nv_bfloat16 l2 = __float2bfloat16(v.z - __bfloat162float(h2));
    __nv_bfloat16 l3 = __float2bfloat16(v.w - __bfloat162float(h3));
    __nv_bfloat16* r = A2 + (size_t)row * PKO;
    uint2 hp, lp;
    ((__nv_bfloat16*)&hp)[0] = h0; ((__nv_bfloat16*)&hp)[1] = h1;
    ((__nv_bfloat16*)&hp)[2] = h2; ((__nv_bfloat16*)&hp)[3] = h3;
    ((__nv_bfloat16*)&lp)[0] = l0; ((__nv_bfloat16*)&lp)[1] = l1;
    ((__nv_bfloat16*)&lp)[2] = l2; ((__nv_bfloat16*)&lp)[3] = l3;
    *(uint2*)(r + base)          = hp;
    *(uint2*)(r + TWO_D + base)  = hp;
    *(uint2*)(r + 2048 + base)   = lp;
}

__global__ void __launch_bounds__(256)
prep_splitBo_kernel(const float* __restrict__ Wr, const float* __restrict__ Wi,
                    __nv_bfloat16* __restrict__ B2)
{
    const int j = blockIdx.x;
    const int n = j >> 1, s = j & 1;
    __nv_bfloat16* r = B2 + (size_t)j * PKO;
    for (int c = threadIdx.x; c < TWO_D; c += 256) {
        int d = c >> 1, p = c & 1;
        float v;
        if (s == 0) v = (p == 0) ? Wr[(size_t)n * DIM + d] : -Wi[(size_t)n * DIM + d];
        else        v = (p == 0) ? Wi[(size_t)n * DIM + d] :  Wr[(size_t)n * DIM + d];
        __nv_bfloat16 h = __float2bfloat16(v);
        __nv_bfloat16 l = __float2bfloat16(v - __bfloat162float(h));
        r[c] = h;
        r[TWO_D + c] = l;
        r[2048 + c] = h;
    }
}

// ---------------- out-projection GEMM (split-bf16, K=3072, x4 B-frag loads) -------------
__global__ void __launch_bounds__(256, 2)
proj_gemm_mma(const __nv_bfloat16* __restrict__ A, const __nv_bfloat16* __restrict__ B,
              const float* __restrict__ br, const float* __restrict__ bi,
              float* __restrict__ C, int kchunks)
{
    extern __shared__ __align__(16) char smraw[];
    const uint32_t sb = smem_u32(smraw);
    const int tid = threadIdx.x;
    const int wid = tid >> 5, lane = tid & 31;
    const int m0 = blockIdx.x * 128;
    const int n0 = blockIdx.y * 128;
    const int wm0 = (wid & 1) * 64, wn0 = (wid >> 1) * 32;
    const size_t rstride = (size_t)kchunks * 128;

    float acc[4][4][4];
#pragma unroll
    for (int a = 0; a < 4; a++)
#pragma unroll
        for (int b = 0; b < 4; b++)
#pragma unroll
            for (int c = 0; c < 4; c++) acc[a][b][c] = 0.f;

    const char* Abase = (const char*)A + (size_t)m0 * rstride;
    const char* Bbase = (const char*)B + (size_t)n0 * rstride;

    gemm_load_stage(Abase, Bbase, rstride, sb, tid, 0, 0);
    int buf = 0;
    const int frow = lane & 15, fcol = (lane >> 4) * 8;

    for (int it = 0; it < kchunks; it++) {
        if (it < kchunks - 1) {
            gemm_load_stage(Abase, Bbase, rstride, sb, tid, it + 1, buf ^ 1);
            asm volatile("cp.async.wait_group 1;" ::: "memory");
        } else {
            asm volatile("cp.async.wait_group 0;" ::: "memory");
        }
        __syncthreads();
        const uint32_t aB = sb + (uint32_t)buf * STAGE_BYTES;
        const uint32_t bB = aB + TILE_BYTES;
#pragma unroll
        for (int ks = 0; ks < 4; ks++) {
            uint32_t afr[4][4], bfr[2][4];
#pragma unroll
            for (int fm = 0; fm < 4; fm++)
                ldmx4(afr[fm], aB + (wm0 + fm * 16 + frow) * 144 + (ks * 16 + fcol) * 2);
#pragma unroll
            for (int g = 0; g < 2; g++)
                ldmx4(bfr[g], bB + (wn0 + g * 16 + frow) * 144 + (ks * 16 + fcol) * 2);
#pragma unroll
            for (int fm = 0; fm < 4; fm++)
#pragma unroll
                for (int fn = 0; fn < 4; fn++) {
                    const int g = fn >> 1, hf = fn & 1;
                    mma_bf16_b2(acc[fm][fn], afr[fm], bfr[g][hf], bfr[g][hf + 2]);
                }
        }
        __syncthreads();
        buf ^= 1;
    }

#pragma unroll
    for (int fm = 0; fm < 4; fm++) {
        int mlo = m0 + wm0 + fm * 16 + (lane >> 2);
        int mhi = mlo + 8;
#pragma unroll
        for (int fn = 0; fn < 4; fn++) {
            int n = n0 + wn0 + fn * 8 + (lane & 3) * 2;
            float b0 = br[n >> 1], b1 = bi[n >> 1];
            float2 vlo = make_float2(acc[fm][fn][0] + b0, acc[fm][fn][1] + b1);
            float2 vhi = make_float2(acc[fm][fn][2] + b0, acc[fm][fn][3] + b1);
            *(float2*)&C[(size_t)mlo * TWO_D + n] = vlo;
            *(float2*)&C[(size_t)mhi * TWO_D + n] = vhi;
        }
    }
}

// ---------------- launch ----------------
extern "C" void kernel_launch(void* const* d_in, const int* in_sizes, int n_in,
                              void* d_out, int out_size)
{
    const float* query = (const float*)d_in[0];
    const float* keys  = (const float*)d_in[1];
    const float* vals  = (const float*)d_in[2];
    const float* Wq_r  = (const float*)d_in[3];
    const float* Wq_i  = (const float*)d_in[4];
    const float* bq_r  = (const float*)d_in[5];
    const float* bq_i  = (const float*)d_in[6];
    const float* Wo_r  = (const float*)d_in[7];
    const float* Wo_i  = (const float*)d_in[8];
    const float* bo_r  = (const float*)d_in[9];
    const float* bo_i  = (const float*)d_in[10];
    const float* gamma = (const float*)d_in[11];
    float* out = (float*)d_out;

    void *p_q, *p_qh, *p_kh, *p_qmd, *p_qmf, *p_kmd, *p_kmf, *p_sc, *p_nrm, *p_A2o, *p_B2o;
    cudaGetSymbolAddress(&p_q,   g_q);
    cudaGetSymbolAddress(&p_qh,  g_qh);
    cudaGetSymbolAddress(&p_kh,  g_kh);
    cudaGetSymbolAddress(&p_qmd, g_qmagd);
    cudaGetSymbolAddress(&p_qmf, g_qmagf);
    cudaGetSymbolAddress(&p_kmd, g_kmagd);
    cudaGetSymbolAddress(&p_kmf, g_kmagf);
    cudaGetSymbolAddress(&p_sc,  g_scoresh);
    cudaGetSymbolAddress(&p_nrm, g_norm);
    cudaGetSymbolAddress(&p_A2o, g_A2o);
    cudaGetSymbolAddress(&p_B2o, g_B2o);
    float*  qbuf  = (float*)p_q;
    __nv_bfloat16* qh = (__nv_bfloat16*)p_qh;
    __nv_bfloat16* kh = (__nv_bfloat16*)p_kh;
    double* qmagd = (double*)p_qmd;
    float*  qmagf = (float*)p_qmf;
    double* kmagd = (double*)p_kmd;
    float*  kmagf = (float*)p_kmf;
    __half* sc    = (__half*)p_sc;
    float*  nrmb  = (float*)p_nrm;
    __nv_bfloat16* A2o = (__nv_bfloat16*)p_A2o;
    __nv_bfloat16* B2o = (__nv_bfloat16*)p_B2o;

    cudaFuncSetAttribute(coh_gemm_mma, cudaFuncAttributeMaxDynamicSharedMemorySize, GEMM_SMEM);
    cudaFuncSetAttribute(proj_gemm_mma, cudaFuncAttributeMaxDynamicSharedMemorySize, PGEMM_SMEM);

    dim3 gproj(DIM / 64, QROWS / 64);

    prep_bf16_kernel<<<NKEYS, 128>>>(keys, kh, kmagd, kmagf);
    prep_splitBo_kernel<<<TWO_D, 256>>>(Wo_r, Wo_i, B2o);

    // precise q projection (block-compensated Kahan, fma pipe)
    cproj_kernel<<<gproj, 256>>>(query, Wq_r, Wq_i, bq_r, bq_i, qbuf);
    prep_bf16_kernel<<<QROWS, 128>>>(qbuf, qh, qmagd, qmagf);

    // coherence screening GEMM
    dim3 ggemm(QROWS / GTM, NKEYS / GTN);
    coh_gemm_mma<<<ggemm, 256, GEMM_SMEM>>>(qh, kh, qmagf, kmagf, sc);

    // top-64 + softmax + gather + phase norm (two-pass, static smem, high occupancy)
    topk_kernel<<<QROWS, 256>>>(sc, qbuf, keys, qmagd, kmagd, vals, gamma, nrmb);

    // output projection (tensor, 3-term split, K=3072)
    prep_splitAo_kernel<<<QROWS, 256>>>(nrmb, A2o);
    dim3 gpro(QROWS / 128, TWO_D / 128);
    proj_gemm_mma<<<gpro, 256, PGEMM_SMEM>>>(A2o, B2o, bo_r, bo_i, out, PKO / 64);
}

// round 17
// speedup vs baseline: 1.2796x; 1.0008x over previous
#include <cuda_runtime.h>
#include <cuda_fp16.h>
#include <cuda_bf16.h>
#include <math.h>
#include <stdint.h>

#define QROWS 4096
#define DIM   512
#define TWO_D 1024
#define NKEYS 32768
#define TOPK  64
#define EPSF  1e-8f
#define NBINS 2048
#define CAP   1024

// ---- coherence GEMM: 128x128 tile, 3-stage cp.async ----
#define GTM 128
#define GTN 128
#define TILE_BYTES (128 * 144)
#define STAGE_BYTES (2 * TILE_BYTES)        // 36864
#define NSTG 3
#define GEMM_SMEM (NSTG * STAGE_BYTES)      // 110592
#define KCHUNKS 16

// ---- out-projection split-bf16 GEMM: K = 3072 ----
#define PKO 3072
#define PGEMM_SMEM (2 * STAGE_BYTES)        // 73728, 2-stage

// ---------------- scratch (no allocations allowed) ----------------
__device__ float  g_q[(size_t)QROWS * TWO_D];
__device__ __nv_bfloat16 g_qh[(size_t)QROWS * TWO_D];
__device__ __nv_bfloat16 g_kh[(size_t)NKEYS * TWO_D];
__device__ double g_qmagd[QROWS];
__device__ float  g_qmagf[QROWS];
__device__ double g_kmagd[NKEYS];
__device__ float  g_kmagf[NKEYS];
__device__ __half g_scoresh[(size_t)QROWS * NKEYS];
__device__ float  g_norm[(size_t)QROWS * TWO_D];
__device__ __nv_bfloat16 g_A2o[(size_t)QROWS * PKO];
__device__ __nv_bfloat16 g_B2o[(size_t)TWO_D * PKO];

// ---------------- helpers ----------------
__device__ __forceinline__ uint32_t smem_u32(const void* p) {
    uint32_t a;
    asm("{ .reg .u64 t; cvta.to.shared.u64 t, %1; cvt.u32.u64 %0, t; }" : "=r"(a) : "l"(p));
    return a;
}
__device__ __forceinline__ void cpasync16(uint32_t dst, const void* src) {
    asm volatile("cp.async.cg.shared.global [%0], [%1], 16;" :: "r"(dst), "l"(src) : "memory");
}
__device__ __forceinline__ void ldmx4(uint32_t* r, uint32_t a) {
    asm volatile("ldmatrix.sync.aligned.m8n8.x4.shared.b16 {%0,%1,%2,%3}, [%4];"
                 : "=r"(r[0]), "=r"(r[1]), "=r"(r[2]), "=r"(r[3]) : "r"(a));
}
__device__ __forceinline__ void mma_bf16_b2(float* d, const uint32_t* a, uint32_t b0, uint32_t b1) {
    asm volatile(
        "mma.sync.aligned.m16n8k16.row.col.f32.bf16.bf16.f32 "
        "{%0,%1,%2,%3}, {%4,%5,%6,%7}, {%8,%9}, {%0,%1,%2,%3};"
        : "+f"(d[0]), "+f"(d[1]), "+f"(d[2]), "+f"(d[3])
        : "r"(a[0]), "r"(a[1]), "r"(a[2]), "r"(a[3]), "r"(b0), "r"(b1));
}

// Kahan add, rounding-mode-pinned
__device__ __forceinline__ void kadd(float& s, float& c, float t) {
    float y = __fsub_rn(t, c);
    float u = __fadd_rn(s, y);
    c = __fsub_rn(__fsub_rn(u, s), y);
    s = u;
}
// compensated product-accumulate (rescore path)
__device__ __forceinline__ void cdot(float& s, float& c, float& es, float a, float b) {
    float p = __fmul_rn(a, b);
    float e = __fmaf_rn(a, b, -p);
    kadd(s, c, p);
    es = __fadd_rn(es, e);
}

// ---------------- precise q projection: block-compensated accumulation ----------------
__global__ void __launch_bounds__(256)
cproj_kernel(const float* __restrict__ X,
             const float* __restrict__ Wr, const float* __restrict__ Wi,
             const float* __restrict__ br, const float* __restrict__ bi,
             float* __restrict__ Y)
{
    __shared__ float2 Xs[16][64];
    __shared__ float2 Ws[16][64];
    const int tid = threadIdx.x;
    const int m0 = blockIdx.y * 64;
    const int n0 = blockIdx.x * 64;
    const int kk = tid & 15;
    const int rr = tid >> 4;
    const int ty4 = (tid >> 4) * 4;
    const int tx4 = (tid & 15) * 4;

    float cr[4][4], ci[4][4], er[4][4], ei[4][4];
#pragma unroll
    for (int i = 0; i < 4; i++)
#pragma unroll
        for (int j = 0; j < 4; j++) { cr[i][j] = 0.f; ci[i][j] = 0.f; er[i][j] = 0.f; ei[i][j] = 0.f; }

    for (int k0 = 0; k0 < DIM; k0 += 16) {
#pragma unroll
        for (int r = 0; r < 4; r++) {
            int row = rr + r * 16;
            Xs[kk][row] = *(const float2*)&X[((size_t)(m0 + row) * DIM + k0 + kk) * 2];
            float wr = Wr[(size_t)(n0 + row) * DIM + k0 + kk];
            float wi = Wi[(size_t)(n0 + row) * DIM + k0 + kk];
            Ws[kk][row] = make_float2(wr, wi);
        }
        __syncthreads();

        float tr[4][4], ti[4][4];
#pragma unroll
        for (int i = 0; i < 4; i++)
#pragma unroll
            for (int j = 0; j < 4; j++) { tr[i][j] = 0.f; ti[i][j] = 0.f; }

#pragma unroll
        for (int k = 0; k < 16; k++) {
            float2 a[4], w[4];
#pragma unroll
            for (int i = 0; i < 4; i++) a[i] = Xs[k][ty4 + i];
#pragma unroll
            for (int j = 0; j < 4; j++) w[j] = Ws[k][tx4 + j];
#pragma unroll
            for (int i = 0; i < 4; i++)
#pragma unroll
                for (int j = 0; j < 4; j++) {
                    tr[i][j] = __fmaf_rn(a[i].x, w[j].x, tr[i][j]);
                    tr[i][j] = __fmaf_rn(-a[i].y, w[j].y, tr[i][j]);
                    ti[i][j] = __fmaf_rn(a[i].x, w[j].y, ti[i][j]);
                    ti[i][j] = __fmaf_rn(a[i].y, w[j].x, ti[i][j]);
                }
        }
#pragma unroll
        for (int i = 0; i < 4; i++)
#pragma unroll
            for (int j = 0; j < 4; j++) {
                kadd(cr[i][j], er[i][j], tr[i][j]);
                kadd(ci[i][j], ei[i][j], ti[i][j]);
            }
        __syncthreads();
    }
#pragma unroll
    for (int i = 0; i < 4; i++) {
        int m = m0 + ty4 + i;
#pragma unroll
        for (int j = 0; j < 4; j++) {
            int n = n0 + tx4 + j;
            Y[((size_t)m * DIM + n) * 2 + 0] = __fadd_rn(cr[i][j], er[i][j]) + br[n];
            Y[((size_t)m * DIM + n) * 2 + 1] = __fadd_rn(ci[i][j], ei[i][j]) + bi[n];
        }
    }
}

// ---------------- fused prep: double mag + fp32 mag + bf16 conversion ----------------
__global__ void __launch_bounds__(128)
prep_bf16_kernel(const float* __restrict__ X, __nv_bfloat16* __restrict__ Xh,
                 double* __restrict__ out_d, float* __restrict__ out_f)
{
    __shared__ double sm[128];
    const int row = blockIdx.x;
    const int tid = threadIdx.x;
    const float* p = X + (size_t)row * TWO_D;
    const int base = tid * 8;

    float4 v0 = *(const float4*)(p + base);
    float4 v1 = *(const float4*)(p + base + 4);

    double s = (double)v0.x * v0.x + (double)v0.y * v0.y
             + (double)v0.z * v0.z + (double)v0.w * v0.w
             + (double)v1.x * v1.x + (double)v1.y * v1.y
             + (double)v1.z * v1.z + (double)v1.w * v1.w;

    __nv_bfloat162 b0 = __float22bfloat162_rn(make_float2(v0.x, v0.y));
    __nv_bfloat162 b1 = __float22bfloat162_rn(make_float2(v0.z, v0.w));
    __nv_bfloat162 b2 = __float22bfloat162_rn(make_float2(v1.x, v1.y));
    __nv_bfloat162 b3 = __float22bfloat162_rn(make_float2(v1.z, v1.w));
    uint4 packed;
    packed.x = *(uint32_t*)&b0; packed.y = *(uint32_t*)&b1;
    packed.z = *(uint32_t*)&b2; packed.w = *(uint32_t*)&b3;
    *(uint4*)(Xh + (size_t)row * TWO_D + base) = packed;

    sm[tid] = s;
    __syncthreads();
    for (int o = 64; o > 0; o >>= 1) {
        if (tid < o) sm[tid] += sm[tid + o];
        __syncthreads();
    }
    if (tid == 0) {
        double m = sqrt(sm[0] + 1e-8);
        out_d[row] = m;
        out_f[row] = (float)m;
    }
}

// ---------------- stage loader (A tile + B tile) ----------------
__device__ __forceinline__ void gemm_load_stage(
    const char* Abase, const char* Bbase, size_t rstride,
    uint32_t sb, int tid, int it, int s)
{
    const int seg = tid & 7;
    const size_t koff = (size_t)it * 128 + (size_t)seg * 16;
    const uint32_t so = sb + (uint32_t)s * STAGE_BYTES;
#pragma unroll
    for (int j = 0; j < 4; j++) {
        int row = (tid >> 3) + 32 * j;
        cpasync16(so + row * 144 + seg * 16, Abase + (size_t)row * rstride + koff);
    }
#pragma unroll
    for (int j = 0; j < 4; j++) {
        int row = (tid >> 3) + 32 * j;
        cpasync16(so + TILE_BYTES + row * 144 + seg * 16, Bbase + (size_t)row * rstride + koff);
    }
    asm volatile("cp.async.commit_group;" ::: "memory");
}

// ---------------- coherence GEMM: 3-stage pipeline, x4 B-frag loads ----------------
__global__ void __launch_bounds__(256, 2)
coh_gemm_mma(const __nv_bfloat16* __restrict__ A, const __nv_bfloat16* __restrict__ B,
             const float* __restrict__ qmag, const float* __restrict__ kmag,
             __half* __restrict__ C)
{
    extern __shared__ __align__(16) char smraw[];
    const uint32_t sb = smem_u32(smraw);
    const int tid = threadIdx.x;
    const int wid = tid >> 5, lane = tid & 31;
    const int m0 = blockIdx.x * GTM;
    const int n0 = blockIdx.y * GTN;
    const int wm0 = (wid & 1) * 64, wn0 = (wid >> 1) * 32;

    float acc[4][4][4];
#pragma unroll
    for (int a = 0; a < 4; a++)
#pragma unroll
        for (int b = 0; b < 4; b++)
#pragma unroll
            for (int c = 0; c < 4; c++) acc[a][b][c] = 0.f;

    const char* Abase = (const char*)A + (size_t)m0 * 2048;
    const char* Bbase = (const char*)B + (size_t)n0 * 2048;

    gemm_load_stage(Abase, Bbase, 2048, sb, tid, 0, 0);
    gemm_load_stage(Abase, Bbase, 2048, sb, tid, 1, 1);

    const int frow = lane & 15, fcol = (lane >> 4) * 8;
    int buf = 0;

    for (int it = 0; it < KCHUNKS; it++) {
        if (it < KCHUNKS - 1) {
            asm volatile("cp.async.wait_group 1;" ::: "memory");
        } else {
            asm volatile("cp.async.wait_group 0;" ::: "memory");
        }
        __syncthreads();
        if (it + 2 < KCHUNKS)
            gemm_load_stage(Abase, Bbase, 2048, sb, tid, it + 2, (it + 2) % NSTG);

        const uint32_t aB = sb + (uint32_t)buf * STAGE_BYTES;
        const uint32_t bB = aB + TILE_BYTES;
#pragma unroll
        for (int ks = 0; ks < 4; ks++) {
            uint32_t afr[4][4], bfr[2][4];
#pragma unroll
            for (int fm = 0; fm < 4; fm++)
                ldmx4(afr[fm], aB + (wm0 + fm * 16 + frow) * 144 + (ks * 16 + fcol) * 2);
#pragma unroll
            for (int g = 0; g < 2; g++)
                ldmx4(bfr[g], bB + (wn0 + g * 16 + frow) * 144 + (ks * 16 + fcol) * 2);
#pragma unroll
            for (int fm = 0; fm < 4; fm++)
#pragma unroll
                for (int fn = 0; fn < 4; fn++) {
                    const int g = fn >> 1, hf = fn & 1;
                    mma_bf16_b2(acc[fm][fn], afr[fm], bfr[g][hf], bfr[g][hf + 2]);
                }
        }
        buf = (buf + 1) % NSTG;
    }

#pragma unroll
    for (int fm = 0; fm < 4; fm++) {
        int mlo = m0 + wm0 + fm * 16 + (lane >> 2);
        int mhi = mlo + 8;
        float qlo = qmag[mlo], qhi = qmag[mhi];
#pragma unroll
        for (int fn = 0; fn < 4; fn++) {
            int n = n0 + wn0 + fn * 8 + (lane & 3) * 2;
            float k0v = kmag[n], k1v = kmag[n + 1];
            __half2 hlo, hhi;
            hlo.x = __float2half_rn(acc[fm][fn][0] / (qlo * k0v + EPSF));
            hlo.y = __float2half_rn(acc[fm][fn][1] / (qlo * k1v + EPSF));
            hhi.x = __float2half_rn(acc[fm][fn][2] / (qhi * k0v + EPSF));
            hhi.y = __float2half_rn(acc[fm][fn][3] / (qhi * k1v + EPSF));
            *(__half2*)&C[(size_t)mlo * NKEYS + n] = hlo;
            *(__half2*)&C[(size_t)mhi * NKEYS + n] = hhi;
        }
    }
}

// ------- top-64 (half2 screen -> float-float rescore -> select) + softmax + gather + norm -----
__global__ void __launch_bounds__(256)
topk_kernel(const __half* __restrict__ scores,
            const float* __restrict__ qbuf,
            const float* __restrict__ keys,
            const double* __restrict__ qmagd,
            const double* __restrict__ kmagd,
            const float* __restrict__ values,
            const float* __restrict__ gamma,
            float* __restrict__ outn)
{
    __shared__ int    hist[NBINS];
    __shared__ int    csum[256];
    __shared__ float  qs[TWO_D];
    __shared__ double cand_d[CAP];
    __shared__ int    cand_i[CAP];
    __shared__ int    s_cnt;
    __shared__ int    s_thresh;
    __shared__ double sel_d[TOPK];
    __shared__ int    sel_i[TOPK];
    __shared__ float  s_w[TOPK];
    __shared__ double redv[8];
    __shared__ int    redi[8];
    __shared__ float  snorm[256];
    __shared__ float  s_inv;

    const int q = blockIdx.x;
    const int tid = threadIdx.x;
    const __half2* row2 = (const __half2*)(scores + (size_t)q * NKEYS);

    for (int i = tid; i < NBINS; i += 256) hist[i] = 0;
    for (int i = tid; i < TWO_D; i += 256) qs[i] = qbuf[(size_t)q * TWO_D + i];
    if (tid == 0) s_cnt = 0;
    __syncthreads();

    for (int i = tid; i < NKEYS / 2; i += 256) {
        float2 s2 = __half22float2(row2[i]);
        int b0 = (int)floorf(__fmaf_rn(s2.x, 1024.f, 1024.f));
        int b1 = (int)floorf(__fmaf_rn(s2.y, 1024.f, 1024.f));
        b0 = max(0, min(NBINS - 1, b0));
        b1 = max(0, min(NBINS - 1, b1));
        atomicAdd(&hist[b0], 1);
        atomicAdd(&hist[b1], 1);
    }
    __syncthreads();

    {
        int c = 0;
#pragma unroll
        for (int j = 0; j < 8; j++) c += hist[tid * 8 + j];
        csum[tid] = c;
    }
    __syncthreads();
    if (tid == 0) {
        int acc = 0, thr = 0;
        for (int ch = 255; ch >= 0; ch--) {
            if (acc + csum[ch] >= TOPK) {
                for (int b = ch * 8 + 7; b >= ch * 8; b--) {
                    acc += hist[b];
                    if (acc >= TOPK) { thr = b; break; }
                }
                break;
            }
            acc += csum[ch];
        }
        s_thresh = max(thr - 2, 0);
    }
    __syncthreads();
    const int thresh = s_thresh;

    for (int i = tid; i < NKEYS / 2; i += 256) {
        float2 s2 = __half22float2(row2[i]);
        int b0 = (int)floorf(__fmaf_rn(s2.x, 1024.f, 1024.f));
        int b1 = (int)floorf(__fmaf_rn(s2.y, 1024.f, 1024.f));
        b0 = max(0, min(NBINS - 1, b0));
        b1 = max(0, min(NBINS - 1, b1));
        if (b0 >= thresh) {
            int pos = atomicAdd(&s_cnt, 1);
            if (pos < CAP) cand_i[pos] = 2 * i;
        }
        if (b1 >= thresh) {
            int pos = atomicAdd(&s_cnt, 1);
            if (pos < CAP) cand_i[pos] = 2 * i + 1;
        }
    }
    __syncthreads();
    const int cnt = min(s_cnt, CAP);

    {
        const int wid = tid >> 5, lane = tid & 31;
        const double qm = qmagd[q];
        for (int c = wid; c < cnt; c += 8) {
            const int ki = cand_i[c];
            const float* kr = keys + (size_t)ki * TWO_D;
            float s = 0.f, comp = 0.f, es = 0.f;
#pragma unroll
            for (int t = 0; t < 8; t++) {
                int e = t * 128 + lane * 4;
                float4 kv = *(const float4*)(kr + e);
                cdot(s, comp, es, qs[e],     kv.x);
                cdot(s, comp, es, qs[e + 1], kv.y);
                cdot(s, comp, es, qs[e + 2], kv.z);
                cdot(s, comp, es, qs[e + 3], kv.w);
            }
            double acc = (double)s + (double)comp + (double)es;
#pragma unroll
            for (int o = 16; o > 0; o >>= 1)
                acc += __shfl_down_sync(0xffffffffu, acc, o);
            if (lane == 0) cand_d[c] = acc / (qm * kmagd[ki] + (double)EPSF);
        }
    }
    __syncthreads();

    for (int t = 0; t < TOPK; t++) {
        double bv = -1e300; int bi = 0;
        for (int i = tid; i < cnt; i += 256) {
            double v = cand_d[i];
            if (v > bv) { bv = v; bi = i; }
        }
#pragma unroll
        for (int o = 16; o > 0; o >>= 1) {
            double ov = __shfl_down_sync(0xffffffffu, bv, o);
            int    oi = __shfl_down_sync(0xffffffffu, bi, o);
            if (ov > bv) { bv = ov; bi = oi; }
        }
        if ((tid & 31) == 0) { redv[tid >> 5] = bv; redi[tid >> 5] = bi; }
        __syncthreads();
        if (tid == 0) {
            double fv = redv[0]; int fi = redi[0];
#pragma unroll
            for (int w = 1; w < 8; w++)
                if (redv[w] > fv) { fv = redv[w]; fi = redi[w]; }
            sel_d[t] = fv; sel_i[t] = cand_i[fi];
            cand_d[fi] = -1e300;
        }
        __syncthreads();
    }

    if (tid == 0) {
        float m = (float)sel_d[0];
        float z = 0.f;
        for (int t = 0; t < TOPK; t++) { float w = expf((float)sel_d[t] - m); s_w[t] = w; z += w; }
        float inv = 1.0f / z;
        for (int t = 0; t < TOPK; t++) s_w[t] *= inv;
    }
    __syncthreads();

    const int col = tid * 4;
    float4 acc = make_float4(0.f, 0.f, 0.f, 0.f);
    for (int t = 0; t < TOPK; t++) {
        const float4 v = *(const float4*)&values[(size_t)sel_i[t] * TWO_D + col];
        float w = s_w[t];
        acc.x += w * v.x; acc.y += w * v.y; acc.z += w * v.z; acc.w += w * v.w;
    }

    snorm[tid] = acc.x * acc.x + acc.y * acc.y + acc.z * acc.z + acc.w * acc.w;
    __syncthreads();
    for (int o = 128; o > 0; o >>= 1) {
        if (tid < o) snorm[tid] += snorm[tid + o];
        __syncthreads();
    }
    if (tid == 0) {
        float mean = snorm[0] / (float)DIM;
        s_inv = 1.0f / sqrtf(mean + EPSF);
    }
    __syncthreads();
    const float inv = s_inv;
    float2 g2 = *(const float2*)&gamma[col >> 1];
    float4 o4;
    o4.x = acc.x * g2.x * inv;
    o4.y = acc.y * g2.x * inv;
    o4.z = acc.z * g2.y * inv;
    o4.w = acc.w * g2.y * inv;
    *(float4*)&outn[(size_t)q * TWO_D + col] = o4;
}

// ---------------- split preps (out-projection) ----------------
__global__ void __launch_bounds__(256)
prep_splitAo_kernel(const float* __restrict__ X, __nv_bfloat16* __restrict__ A2)
{
    const int row = blockIdx.x;
    const int base = threadIdx.x * 4;
    float4 v = *(const float4*)&X[(size_t)row * TWO_D + base];
    __nv_bfloat16 h0 = __float2bfloat16(v.x), h1 = __float2bfloat16(v.y);
    __nv_bfloat16 h2 = __float2bfloat16(v.z), h3 = __float2bfloat16(v.w);
    __nv_bfloat16 l0 = __float2bfloat16(v.x - __bfloat162float(h0));
    __nv_bfloat16 l1 = __float2bfloat16(v.y - __bfloat162float(h1));
    __nv_bfloat16 l2 = __float2bfloat16(v.z - __bfloat162float(h2));
    __nv_bfloat16 l3 = __float2bfloat16(v.w - __bfloat162float(h3));
    __nv_bfloat16* r = A2 + (size_t)row * PKO;
    uint2 hp, lp;
    ((__nv_bfloat16*)&hp)[0] = h0; ((__nv_bfloat16*)&hp)[1] = h1;
    ((__nv_bfloat16*)&hp)[2] = h2; ((__nv_bfloat16*)&hp)[3] = h3;
    ((__nv_bfloat16*)&lp)[0] = l0; ((__nv_bfloat16*)&lp)[1] = l1;
    ((__nv_bfloat16*)&lp)[2] = l2; ((__nv_bfloat16*)&lp)[3] = l3;
    *(uint2*)(r + base)          = hp;
    *(uint2*)(r + TWO_D + base)  = hp;
    *(uint2*)(r + 2048 + base)   = lp;
}

__global__ void __launch_bounds__(256)
prep_splitBo_kernel(const float* __restrict__ Wr, const float* __restrict__ Wi,
                    __nv_bfloat16* __restrict__ B2)
{
    const int j = blockIdx.x;
    const int n = j >> 1, s = j & 1;
    __nv_bfloat16* r = B2 + (size_t)j * PKO;
    for (int c = threadIdx.x; c < TWO_D; c += 256) {
        int d = c >> 1, p = c & 1;
        float v;
        if (s == 0) v = (p == 0) ? Wr[(size_t)n * DIM + d] : -Wi[(size_t)n * DIM + d];
        else        v = (p == 0) ? Wi[(size_t)n * DIM + d] :  Wr[(size_t)n * DIM + d];
        __nv_bfloat16 h = __float2bfloat16(v);
        __nv_bfloat16 l = __float2bfloat16(v - __bfloat162float(h));
        r[c] = h;
        r[TWO_D + c] = l;
        r[2048 + c] = h;
    }
}

// ---------------- out-projection GEMM (split-bf16, K=3072, x4 B-frag loads) -------------
__global__ void __launch_bounds__(256, 2)
proj_gemm_mma(const __nv_bfloat16* __restrict__ A, const __nv_bfloat16* __restrict__ B,
              const float* __restrict__ br, const float* __restrict__ bi,
              float* __restrict__ C, int kchunks)
{
    extern __shared__ __align__(16) char smraw[];
    const uint32_t sb = smem_u32(smraw);
    const int tid = threadIdx.x;
    const int wid = tid >> 5, lane = tid & 31;
    const int m0 = blockIdx.x * 128;
    const int n0 = blockIdx.y * 128;
    const int wm0 = (wid & 1) * 64, wn0 = (wid >> 1) * 32;
    const size_t rstride = (size_t)kchunks * 128;

    float acc[4][4][4];
#pragma unroll
    for (int a = 0; a < 4; a++)
#pragma unroll
        for (int b = 0; b < 4; b++)
#pragma unroll
            for (int c = 0; c < 4; c++) acc[a][b][c] = 0.f;

    const char* Abase = (const char*)A + (size_t)m0 * rstride;
    const char* Bbase = (const char*)B + (size_t)n0 * rstride;

    gemm_load_stage(Abase, Bbase, rstride, sb, tid, 0, 0);
    int buf = 0;
    const int frow = lane & 15, fcol = (lane >> 4) * 8;

    for (int it = 0; it < kchunks; it++) {
        if (it < kchunks - 1) {
            gemm_load_stage(Abase, Bbase, rstride, sb, tid, it + 1, buf ^ 1);
            asm volatile("cp.async.wait_group 1;" ::: "memory");
        } else {
            asm volatile("cp.async.wait_group 0;" ::: "memory");
        }
        __syncthreads();
        const uint32_t aB = sb + (uint32_t)buf * STAGE_BYTES;
        const uint32_t bB = aB + TILE_BYTES;
#pragma unroll
        for (int ks = 0; ks < 4; ks++) {
            uint32_t afr[4][4], bfr[2][4];
#pragma unroll
            for (int fm = 0; fm < 4; fm++)
                ldmx4(afr[fm], aB + (wm0 + fm * 16 + frow) * 144 + (ks * 16 + fcol) * 2);
#pragma unroll
            for (int g = 0; g < 2; g++)
                ldmx4(bfr[g], bB + (wn0 + g * 16 + frow) * 144 + (ks * 16 + fcol) * 2);
#pragma unroll
            for (int fm = 0; fm < 4; fm++)
#pragma unroll
                for (int fn = 0; fn < 4; fn++) {
                    const int g = fn >> 1, hf = fn & 1;
                    mma_bf16_b2(acc[fm][fn], afr[fm], bfr[g][hf], bfr[g][hf + 2]);
                }
        }
        __syncthreads();
        buf ^= 1;
    }

#pragma unroll
    for (int fm = 0; fm < 4; fm++) {
        int mlo = m0 + wm0 + fm * 16 + (lane >> 2);
        int mhi = mlo + 8;
#pragma unroll
        for (int fn = 0; fn < 4; fn++) {
            int n = n0 + wn0 + fn * 8 + (lane & 3) * 2;
            float b0 = br[n >> 1], b1 = bi[n >> 1];
            float2 vlo = make_float2(acc[fm][fn][0] + b0, acc[fm][fn][1] + b1);
            float2 vhi = make_float2(acc[fm][fn][2] + b0, acc[fm][fn][3] + b1);
            *(float2*)&C[(size_t)mlo * TWO_D + n] = vlo;
            *(float2*)&C[(size_t)mhi * TWO_D + n] = vhi;
        }
    }
}

// ---------------- launch ----------------
extern "C" void kernel_launch(void* const* d_in, const int* in_sizes, int n_in,
                              void* d_out, int out_size)
{
    const float* query = (const float*)d_in[0];
    const float* keys  = (const float*)d_in[1];
    const float* vals  = (const float*)d_in[2];
    const float* Wq_r  = (const float*)d_in[3];
    const float* Wq_i  = (const float*)d_in[4];
    const float* bq_r  = (const float*)d_in[5];
    const float* bq_i  = (const float*)d_in[6];
    const float* Wo_r  = (const float*)d_in[7];
    const float* Wo_i  = (const float*)d_in[8];
    const float* bo_r  = (const float*)d_in[9];
    const float* bo_i  = (const float*)d_in[10];
    const float* gamma = (const float*)d_in[11];
    float* out = (float*)d_out;

    void *p_q, *p_qh, *p_kh, *p_qmd, *p_qmf, *p_kmd, *p_kmf, *p_sc, *p_nrm, *p_A2o, *p_B2o;
    cudaGetSymbolAddress(&p_q,   g_q);
    cudaGetSymbolAddress(&p_qh,  g_qh);
    cudaGetSymbolAddress(&p_kh,  g_kh);
    cudaGetSymbolAddress(&p_qmd, g_qmagd);
    cudaGetSymbolAddress(&p_qmf, g_qmagf);
    cudaGetSymbolAddress(&p_kmd, g_kmagd);
    cudaGetSymbolAddress(&p_kmf, g_kmagf);
    cudaGetSymbolAddress(&p_sc,  g_scoresh);
    cudaGetSymbolAddress(&p_nrm, g_norm);
    cudaGetSymbolAddress(&p_A2o, g_A2o);
    cudaGetSymbolAddress(&p_B2o, g_B2o);
    float*  qbuf  = (float*)p_q;
    __nv_bfloat16* qh = (__nv_bfloat16*)p_qh;
    __nv_bfloat16* kh = (__nv_bfloat16*)p_kh;
    double* qmagd = (double*)p_qmd;
    float*  qmagf = (float*)p_qmf;
    double* kmagd = (double*)p_kmd;
    float*  kmagf = (float*)p_kmf;
    __half* sc    = (__half*)p_sc;
    float*  nrmb  = (float*)p_nrm;
    __nv_bfloat16* A2o = (__nv_bfloat16*)p_A2o;
    __nv_bfloat16* B2o = (__nv_bfloat16*)p_B2o;

    cudaFuncSetAttribute(coh_gemm_mma, cudaFuncAttributeMaxDynamicSharedMemorySize, GEMM_SMEM);
    cudaFuncSetAttribute(proj_gemm_mma, cudaFuncAttributeMaxDynamicSharedMemorySize, PGEMM_SMEM);

    dim3 gproj(DIM / 64, QROWS / 64);

    prep_bf16_kernel<<<NKEYS, 128>>>(keys, kh, kmagd, kmagf);
    prep_splitBo_kernel<<<TWO_D, 256>>>(Wo_r, Wo_i, B2o);

    // precise q projection (block-compensated Kahan, fma pipe)
    cproj_kernel<<<gproj, 256>>>(query, Wq_r, Wq_i, bq_r, bq_i, qbuf);
    prep_bf16_kernel<<<QROWS, 128>>>(qbuf, qh, qmagd, qmagf);

    // coherence screening GEMM
    dim3 ggemm(QROWS / GTM, NKEYS / GTN);
    coh_gemm_mma<<<ggemm, 256, GEMM_SMEM>>>(qh, kh, qmagf, kmagf, sc);

    // top-64 + softmax + gather + phase norm (two-pass, static smem, high occupancy)
    topk_kernel<<<QROWS, 256>>>(sc, qbuf, keys, qmagd, kmagd, vals, gamma, nrmb);

    // output projection (tensor, 3-term split, K=3072)
    prep_splitAo_kernel<<<QROWS, 256>>>(nrmb, A2o);
    dim3 gpro(QROWS / 128, TWO_D / 128);
    proj_gemm_mma<<<gpro, 256, PGEMM_SMEM>>>(A2o, B2o, bo_r, bo_i, out, PKO / 64);
}